// round 2
// baseline (speedup 1.0000x reference)
#include <cuda_runtime.h>
#include <math.h>

#define NN   30000
#define TT   16
#define DE   32
#define HE   128
#define F3   384
#define NE0  300000
#define NE   330000
#define NT   3000
#define HD   256
#define OUTL 25

// ---------------- scratch (static device arrays; no allocations) ----------------
__device__ __align__(256) float g_EMB[NN*TT*DE];
__device__ __align__(256) float g_H[NN*HE];
__device__ __align__(256) float g_GH[NN*F3];
__device__ __align__(256) float g_HENC[NN*HE];
__device__ __align__(256) float g_F1[NN*F3];
__device__ __align__(256) float g_O1[NN*F3];
__device__ __align__(256) float g_F2[NN*F3];
__device__ __align__(256) float g_O2[NN*F3];
__device__ __align__(256) float g_asv[NN*3];
__device__ __align__(256) float g_adv[NN*3];
__device__ __align__(256) float g_ENC[NT*HE];
__device__ __align__(256) float g_X0[NT*4*HD];
__device__ __align__(256) float g_G[NT*4*HD];
__device__ __align__(256) float g_h0[NT*HD];
__device__ __align__(256) float g_c0[NT*HD];
__device__ __align__(256) float g_h1[NT*HD];
__device__ __align__(256) float g_c1[NT*HD];
__device__ int g_cnt[NN];
__device__ int g_offs[NN+1];
__device__ int g_cur[NN];
__device__ int g_ssrc[NE];

__device__ __forceinline__ float sigf(float x){ return 1.f/(1.f+__expf(-x)); }
__device__ __forceinline__ float lk01(float x){ return x>=0.f? x : 0.1f*x; }

// ---------------- utility ----------------
__global__ void zero_f(float* __restrict__ p, long n){
    long i = (long)blockIdx.x*blockDim.x + threadIdx.x;
    if (i < n) p[i] = 0.f;
}
__global__ void zero_i(int* __restrict__ p, int n){
    int i = blockIdx.x*blockDim.x + threadIdx.x;
    if (i < n) p[i] = 0;
}

// ---------------- generic fp32 tiled GEMM ----------------
// C[M,N] = act( A[M,Ka]@W1[Ka,N] (+ B2[M,Kb]@W2[Kb,N]) (+bias[N]) (+add[M,N]) )
// optional row gather on A via rowidx. PRE: leaky(0.1) applied to A on load.
// Requirements: K % 16 == 0, N % 64 == 0.
#define BM 64
#define BN 64
#define BK 16
#define SPAD 4

template<int PRE, int ACT>
__global__ void gemm_k(const float* __restrict__ A,  const float* __restrict__ W1, int Ka,
                       const float* __restrict__ B2, const float* __restrict__ W2, int Kb,
                       const float* __restrict__ bias, const float* __restrict__ add,
                       const int* __restrict__ rowidx,
                       float* __restrict__ C, int M, int N)
{
    __shared__ float As[BK][BM+SPAD];
    __shared__ float Ws[BK][BN+SPAD];
    const int bm = blockIdx.y * BM, bn = blockIdx.x * BN;
    const int tid = threadIdx.x;
    const int tx = tid & 15, ty = tid >> 4;

    float acc[4][4] = {};

    const int ar = tid >> 2;            // 0..63 (row of A tile)
    const int ak = (tid & 3) << 2;      // 0,4,8,12 (k offset, float4)
    const int wk = tid >> 4;            // 0..15 (k row of W tile)
    const int wn = (tid & 15) << 2;     // 0..60 (col, float4)

    const int arow_g = bm + ar;
    long arow = -1;
    if (arow_g < M) arow = rowidx ? (long)rowidx[arow_g] : (long)arow_g;

    #pragma unroll
    for (int pass = 0; pass < 2; ++pass) {
        const float* Ap = pass ? B2 : A;
        const float* Wp = pass ? W2 : W1;
        const int K = pass ? Kb : Ka;
        if (Ap == nullptr) continue;
        for (int k0 = 0; k0 < K; k0 += BK) {
            float4 av = make_float4(0.f,0.f,0.f,0.f);
            if (arow >= 0) av = *(const float4*)(Ap + arow*(long)K + k0 + ak);
            if (PRE && pass == 0) { av.x=lk01(av.x); av.y=lk01(av.y); av.z=lk01(av.z); av.w=lk01(av.w); }
            As[ak  ][ar] = av.x;
            As[ak+1][ar] = av.y;
            As[ak+2][ar] = av.z;
            As[ak+3][ar] = av.w;
            float4 wv = *(const float4*)(Wp + (long)(k0+wk)*N + bn + wn);
            *(float4*)&Ws[wk][wn] = wv;
            __syncthreads();
            #pragma unroll
            for (int k = 0; k < BK; ++k) {
                float4 a4 = *(const float4*)&As[k][ty<<2];
                float4 b4 = *(const float4*)&Ws[k][tx<<2];
                acc[0][0]+=a4.x*b4.x; acc[0][1]+=a4.x*b4.y; acc[0][2]+=a4.x*b4.z; acc[0][3]+=a4.x*b4.w;
                acc[1][0]+=a4.y*b4.x; acc[1][1]+=a4.y*b4.y; acc[1][2]+=a4.y*b4.z; acc[1][3]+=a4.y*b4.w;
                acc[2][0]+=a4.z*b4.x; acc[2][1]+=a4.z*b4.y; acc[2][2]+=a4.z*b4.z; acc[2][3]+=a4.z*b4.w;
                acc[3][0]+=a4.w*b4.x; acc[3][1]+=a4.w*b4.y; acc[3][2]+=a4.w*b4.z; acc[3][3]+=a4.w*b4.w;
            }
            __syncthreads();
        }
    }

    #pragma unroll
    for (int i = 0; i < 4; ++i) {
        int row = bm + (ty<<2) + i;
        if (row >= M) continue;
        #pragma unroll
        for (int j = 0; j < 4; ++j) {
            int col = bn + (tx<<2) + j;
            float v = acc[i][j];
            if (bias) v += bias[col];
            if (add)  v += add[(long)row*N + col];
            if (ACT == 1) v = lk01(v);
            C[(long)row*N + col] = v;
        }
    }
}

// ---------------- encoder ----------------
// EMB = leaky0.1( x @ ipW + ipb ), x flattened [NN*TT, 2]
__global__ void emb_kernel(const float* __restrict__ x, const float* __restrict__ ipW,
                           const float* __restrict__ ipb)
{
    long i = (long)blockIdx.x*blockDim.x + threadIdx.x;
    if (i >= (long)NN*TT*DE) return;
    long row = i >> 5; int j = (int)(i & 31);
    float v = x[row*2]*ipW[j] + x[row*2+1]*ipW[DE+j] + ipb[j];
    g_EMB[i] = lk01(v);
}

// GRU gate: fuses x-projection (emb[32] @ Wx columns) + gate nonlinearity.
__global__ void gru_gate(const float* __restrict__ Wx, const float* __restrict__ bx, int t)
{
    int i = blockIdx.x*blockDim.x + threadIdx.x;
    if (i >= NN*HE) return;
    int node = i >> 7, j = i & 127;
    const float* e = g_EMB + ((long)node*TT + t)*DE;
    float gr = bx[j], gz = bx[HE+j], gn = bx[2*HE+j];
    #pragma unroll
    for (int k = 0; k < DE; ++k) {
        float ev = e[k];
        const float* wr = Wx + k*F3;
        gr += ev*wr[j]; gz += ev*wr[HE+j]; gn += ev*wr[2*HE+j];
    }
    const float* gh = g_GH + (long)node*F3;
    float r = sigf(gr + gh[j]);
    float z = sigf(gz + gh[HE+j]);
    float n = tanhf(gn + r*gh[2*HE+j]);
    float h = g_H[i];
    g_H[i] = (1.f - z)*n + z*h;
}

// ---------------- CSR build (dst-sorted edges; self-loops appended) ----------------
__global__ void edge_count(const int* __restrict__ ei){
    int e = blockIdx.x*blockDim.x + threadIdx.x;
    if (e >= NE) return;
    int d = (e < NE0) ? ei[NE0+e] : (e - NE0);
    atomicAdd(&g_cnt[d], 1);
}
__global__ void scan_kernel(){
    __shared__ int sh[1024];
    __shared__ int run;
    int tid = threadIdx.x;
    if (tid == 0) run = 0;
    __syncthreads();
    for (int base = 0; base < NN; base += 1024) {
        int v = (base + tid < NN) ? g_cnt[base + tid] : 0;
        sh[tid] = v; __syncthreads();
        for (int off = 1; off < 1024; off <<= 1) {
            int tv = (tid >= off) ? sh[tid-off] : 0;
            __syncthreads();
            sh[tid] += tv;
            __syncthreads();
        }
        if (base + tid < NN) g_offs[base + tid + 1] = run + sh[tid];
        __syncthreads();
        if (tid == 0) run += sh[1023];
        __syncthreads();
    }
    if (tid == 0) g_offs[0] = 0;
}
__global__ void copy_cur(){
    int i = blockIdx.x*blockDim.x + threadIdx.x;
    if (i < NN) g_cur[i] = g_offs[i];
}
__global__ void edge_scatter(const int* __restrict__ ei){
    int e = blockIdx.x*blockDim.x + threadIdx.x;
    if (e >= NE) return;
    int s, d;
    if (e < NE0) { s = ei[e]; d = ei[NE0+e]; } else { s = e - NE0; d = s; }
    int pos = atomicAdd(&g_cur[d], 1);
    g_ssrc[pos] = s;
}

// ---------------- GAT ----------------
// per (node, head): asv = <F_row_head, a_src[h]>, adv = <F_row_head, a_dst[h]>
__global__ void attn_coef(const float* __restrict__ F, const float* __restrict__ a_s,
                          const float* __restrict__ a_d)
{
    int w = (blockIdx.x*blockDim.x + threadIdx.x) >> 5;
    if (w >= NN*3) return;
    int lane = threadIdx.x & 31;
    int node = w / 3, h = w - node*3;
    const float* f = F + (long)node*F3 + h*HE;
    const float* As_ = a_s + h*HE;
    const float* Ad_ = a_d + h*HE;
    float s1 = 0.f, s2 = 0.f;
    #pragma unroll
    for (int c = lane; c < HE; c += 32) { float fv = f[c]; s1 += fv*As_[c]; s2 += fv*Ad_[c]; }
    #pragma unroll
    for (int o = 16; o; o >>= 1) {
        s1 += __shfl_down_sync(0xffffffffu, s1, o);
        s2 += __shfl_down_sync(0xffffffffu, s2, o);
    }
    if (lane == 0) { g_asv[w] = s1; g_adv[w] = s2; }
}

// one warp per dst node, online softmax over its in-edges, 3 heads x 128 cols
__global__ void gat_agg(const float* __restrict__ F, const float* __restrict__ bias,
                        float* __restrict__ O)
{
    int w = (blockIdx.x*blockDim.x + threadIdx.x) >> 5;
    if (w >= NN) return;
    int lane = threadIdx.x & 31;
    int beg = g_offs[w], end = g_offs[w+1];
    float ad0 = g_adv[w*3], ad1 = g_adv[w*3+1], ad2 = g_adv[w*3+2];
    float m0 = -1e30f, m1 = -1e30f, m2 = -1e30f;
    float d0 = 0.f, d1 = 0.f, d2 = 0.f;
    float acc[12];
    #pragma unroll
    for (int q = 0; q < 12; ++q) acc[q] = 0.f;

    for (int p = beg; p < end; ++p) {
        int s = g_ssrc[p];
        float e0 = g_asv[s*3]   + ad0; e0 = (e0 >= 0.f) ? e0 : 0.2f*e0;
        float e1 = g_asv[s*3+1] + ad1; e1 = (e1 >= 0.f) ? e1 : 0.2f*e1;
        float e2 = g_asv[s*3+2] + ad2; e2 = (e2 >= 0.f) ? e2 : 0.2f*e2;
        const float* f = F + (long)s*F3;
        // head 0
        {
            float nm = fmaxf(m0, e0); float sc = __expf(m0-nm); float wv = __expf(e0-nm);
            d0 = d0*sc + wv;
            #pragma unroll
            for (int q = 0; q < 4; ++q) acc[q] = acc[q]*sc + wv*f[q*32 + lane];
            m0 = nm;
        }
        // head 1
        {
            float nm = fmaxf(m1, e1); float sc = __expf(m1-nm); float wv = __expf(e1-nm);
            d1 = d1*sc + wv;
            #pragma unroll
            for (int q = 0; q < 4; ++q) acc[4+q] = acc[4+q]*sc + wv*f[HE + q*32 + lane];
            m1 = nm;
        }
        // head 2
        {
            float nm = fmaxf(m2, e2); float sc = __expf(m2-nm); float wv = __expf(e2-nm);
            d2 = d2*sc + wv;
            #pragma unroll
            for (int q = 0; q < 4; ++q) acc[8+q] = acc[8+q]*sc + wv*f[2*HE + q*32 + lane];
            m2 = nm;
        }
    }
    float* o = O + (long)w*F3;
    #pragma unroll
    for (int q = 0; q < 4; ++q) {
        int c0 = q*32 + lane;
        o[c0]        = acc[q]  /d0 + bias[c0];
        o[HE + c0]   = acc[4+q]/d1 + bias[HE + c0];
        o[2*HE + c0] = acc[8+q]/d2 + bias[2*HE + c0];
    }
}

// ---------------- decoder ----------------
__global__ void lstm_gate(const float* __restrict__ G, float* __restrict__ h, float* __restrict__ c)
{
    int i = blockIdx.x*blockDim.x + threadIdx.x;
    if (i >= NT*HD) return;
    int b = i >> 8, j = i & 255;
    const float* g = G + (long)b*(4*HD);
    float ig = sigf(g[j]);
    float fg = sigf(g[HD+j]);
    float gg = tanhf(g[2*HD+j]);
    float og = sigf(g[3*HD+j]);
    float cc = fg*c[i] + ig*gg;
    c[i] = cc;
    h[i] = og*tanhf(cc);
}

__global__ void out_head(const float* __restrict__ opW, const float* __restrict__ opb,
                         float* __restrict__ out, int t)
{
    int w = (blockIdx.x*blockDim.x + threadIdx.x) >> 5;
    if (w >= NT) return;
    int lane = threadIdx.x & 31;
    const float* h = g_h1 + (long)w*HD;
    float s0 = 0.f, s1 = 0.f;
    #pragma unroll
    for (int k = lane; k < HD; k += 32) {
        float hv = h[k];
        s0 += hv*opW[k*2];
        s1 += hv*opW[k*2+1];
    }
    #pragma unroll
    for (int o = 16; o; o >>= 1) {
        s0 += __shfl_down_sync(0xffffffffu, s0, o);
        s1 += __shfl_down_sync(0xffffffffu, s1, o);
    }
    if (lane == 0) {
        long base = ((long)w*OUTL + t)*2;
        out[base]   = s0 + opb[0];
        out[base+1] = s1 + opb[1];
    }
}

// ---------------- host orchestration ----------------
static inline void gemm(const float* A, const float* W1, int Ka,
                        const float* B2, const float* W2, int Kb,
                        const float* bias, const float* add, const int* ridx,
                        float* C, int M, int N, int pre, int act)
{
    dim3 g(N/BN, (M + BM - 1)/BM);
    if (pre)       gemm_k<1,1><<<g,256>>>(A,W1,Ka,B2,W2,Kb,bias,add,ridx,C,M,N);
    else if (act)  gemm_k<0,1><<<g,256>>>(A,W1,Ka,B2,W2,Kb,bias,add,ridx,C,M,N);
    else           gemm_k<0,0><<<g,256>>>(A,W1,Ka,B2,W2,Kb,bias,add,ridx,C,M,N);
}

extern "C" void kernel_launch(void* const* d_in, const int* in_sizes, int n_in,
                              void* d_out, int out_size)
{
    const float* x    = (const float*)d_in[0];
    const int*   ei   = (const int*)  d_in[1];
    const int*   tgt  = (const int*)  d_in[2];
    const float* ipW  = (const float*)d_in[3];
    const float* ipb  = (const float*)d_in[4];
    const float* gWx  = (const float*)d_in[5];
    const float* gWh  = (const float*)d_in[6];
    const float* gbx  = (const float*)d_in[7];
    const float* gbh  = (const float*)d_in[8];
    const float* dynW = (const float*)d_in[9];
    const float* dynb = (const float*)d_in[10];
    const float* g1W  = (const float*)d_in[11];
    const float* g1as = (const float*)d_in[12];
    const float* g1ad = (const float*)d_in[13];
    const float* g1b  = (const float*)d_in[14];
    const float* g2W  = (const float*)d_in[15];
    const float* g2as = (const float*)d_in[16];
    const float* g2ad = (const float*)d_in[17];
    const float* g2b  = (const float*)d_in[18];
    const float* fcW  = (const float*)d_in[19];
    const float* fcb  = (const float*)d_in[20];
    const float* l0Wx = (const float*)d_in[21];
    const float* l0Wh = (const float*)d_in[22];
    const float* l0b  = (const float*)d_in[23];
    const float* l1Wx = (const float*)d_in[24];
    const float* l1Wh = (const float*)d_in[25];
    const float* l1b  = (const float*)d_in[26];
    const float* opW  = (const float*)d_in[27];
    const float* opb  = (const float*)d_in[28];
    float* out = (float*)d_out;
    (void)in_sizes; (void)n_in; (void)out_size;

    float *EMB,*H,*GH,*HENC,*F1,*O1,*F2,*O2,*ENC,*X0,*G,*h0,*c0,*h1,*c1;
    cudaGetSymbolAddress((void**)&EMB,  g_EMB);
    cudaGetSymbolAddress((void**)&H,    g_H);
    cudaGetSymbolAddress((void**)&GH,   g_GH);
    cudaGetSymbolAddress((void**)&HENC, g_HENC);
    cudaGetSymbolAddress((void**)&F1,   g_F1);
    cudaGetSymbolAddress((void**)&O1,   g_O1);
    cudaGetSymbolAddress((void**)&F2,   g_F2);
    cudaGetSymbolAddress((void**)&O2,   g_O2);
    cudaGetSymbolAddress((void**)&ENC,  g_ENC);
    cudaGetSymbolAddress((void**)&X0,   g_X0);
    cudaGetSymbolAddress((void**)&G,    g_G);
    cudaGetSymbolAddress((void**)&h0,   g_h0);
    cudaGetSymbolAddress((void**)&c0,   g_c0);
    cudaGetSymbolAddress((void**)&h1,   g_h1);
    cudaGetSymbolAddress((void**)&c1,   g_c1);
    int *cntp;
    cudaGetSymbolAddress((void**)&cntp, g_cnt);

    // ---- CSR build (depends only on edge_index) ----
    zero_i<<<(NN+255)/256,256>>>(cntp, NN);
    edge_count<<<(NE+255)/256,256>>>(ei);
    scan_kernel<<<1,1024>>>();
    copy_cur<<<(NN+255)/256,256>>>();
    edge_scatter<<<(NE+255)/256,256>>>(ei);

    // ---- encoder: emb + GRU ----
    emb_kernel<<<(int)(((long)NN*TT*DE + 255)/256),256>>>(x, ipW, ipb);
    zero_f<<<(int)(((long)NN*HE + 255)/256),256>>>(H, (long)NN*HE);
    for (int t = 0; t < TT; ++t) {
        gemm(H, gWh, HE, nullptr, nullptr, 0, gbh, nullptr, nullptr, GH, NN, F3, 0, 0);
        gru_gate<<<(NN*HE+255)/256,256>>>(gWx, gbx, t);
    }
    // hist_enc = leaky( leaky(H) @ dynW + dynb )
    gemm(H, dynW, HE, nullptr, nullptr, 0, dynb, nullptr, nullptr, HENC, NN, HE, 1, 1);

    // ---- GAT layer 1 ----
    gemm(HENC, g1W, HE, nullptr, nullptr, 0, nullptr, nullptr, nullptr, F1, NN, F3, 0, 0);
    attn_coef<<<(NN*3*32+255)/256,256>>>(F1, g1as, g1ad);
    gat_agg<<<(NN*32+255)/256,256>>>(F1, g1b, O1);

    // ---- GAT layer 2 ----
    gemm(O1, g2W, F3, nullptr, nullptr, 0, nullptr, nullptr, nullptr, F2, NN, F3, 0, 0);
    attn_coef<<<(NN*3*32+255)/256,256>>>(F2, g2as, g2ad);
    gat_agg<<<(NN*32+255)/256,256>>>(F2, g2b, O2);

    // ---- target gather + fc ----
    gemm(O2, fcW, F3, nullptr, nullptr, 0, fcb, nullptr, tgt, ENC, NT, HE, 0, 1);

    // ---- decoder ----
    gemm(ENC, l0Wx, HE, nullptr, nullptr, 0, l0b, nullptr, nullptr, X0, NT, 4*HD, 0, 0);
    zero_f<<<((NT*HD)+255)/256,256>>>(h0, (long)NT*HD);
    zero_f<<<((NT*HD)+255)/256,256>>>(c0, (long)NT*HD);
    zero_f<<<((NT*HD)+255)/256,256>>>(h1, (long)NT*HD);
    zero_f<<<((NT*HD)+255)/256,256>>>(c1, (long)NT*HD);

    for (int t = 0; t < OUTL; ++t) {
        // layer 0: G = X0 + h0 @ l0_Wh   (X0 already contains x-part + bias)
        gemm(h0, l0Wh, HD, nullptr, nullptr, 0, nullptr, X0, nullptr, G, NT, 4*HD, 0, 0);
        lstm_gate<<<(NT*HD+255)/256,256>>>(G, h0, c0);
        // layer 1: G = h0 @ l1_Wx + h1 @ l1_Wh + l1_b
        gemm(h0, l1Wx, HD, h1, l1Wh, HD, l1b, nullptr, nullptr, G, NT, 4*HD, 0, 0);
        lstm_gate<<<(NT*HD+255)/256,256>>>(G, h1, c1);
        out_head<<<(NT*32+255)/256,256>>>(opW, opb, out, t);
    }
}

// round 4
// speedup vs baseline: 1.5903x; 1.5903x over previous
#include <cuda_runtime.h>
#include <cuda_bf16.h>
#include <mma.h>
#include <math.h>
#include <stdint.h>

using namespace nvcuda;

#define NN   30000
#define TT   16
#define DE   32
#define HE   128
#define F3   384
#define NE0  300000
#define NE   330000
#define NT   3000
#define HD   256
#define OUTL 25

// ---------------- scratch (static device arrays; no allocations) ----------------
__device__ __align__(256) float g_EMB[NN*TT*DE];
__device__ __align__(256) float g_H[NN*HE];
__device__ __align__(256) float g_GH[NN*F3];
__device__ __align__(256) float g_HENC[NN*HE];
__device__ __align__(256) float g_F1[NN*F3];
__device__ __align__(256) float g_O1[NN*F3];
__device__ __align__(256) float g_F2[NN*F3];
__device__ __align__(256) float g_O2[NN*F3];
__device__ __align__(256) float g_asv[NN*3];
__device__ __align__(256) float g_adv[NN*3];
__device__ __align__(256) float g_ENC[NT*HE];
__device__ __align__(256) float g_X0[NT*4*HD];
__device__ __align__(256) float g_G[NT*4*HD];
__device__ __align__(256) float g_h0[NT*HD];
__device__ __align__(256) float g_c0[NT*HD];
__device__ __align__(256) float g_h1[NT*HD];
__device__ __align__(256) float g_c1[NT*HD];
__device__ int g_cnt[NN];
__device__ int g_offs[NN+1];
__device__ int g_cur[NN];
__device__ int g_ssrc[NE];
// transposed bf16 hi/lo weights [N,K]
#define WT_TOTAL 1163264
__device__ __align__(256) __nv_bfloat16 g_WThi[WT_TOTAL];
__device__ __align__(256) __nv_bfloat16 g_WTlo[WT_TOTAL];

__device__ __forceinline__ float sigf(float x){ return 1.f/(1.f+__expf(-x)); }
__device__ __forceinline__ float lk01(float x){ return x>=0.f? x : 0.1f*x; }

// ---------------- utility ----------------
__global__ void zero_f(float* __restrict__ p, long n){
    long i = (long)blockIdx.x*blockDim.x + threadIdx.x;
    if (i < n) p[i] = 0.f;
}
__global__ void zero_i(int* __restrict__ p, int n){
    int i = blockIdx.x*blockDim.x + threadIdx.x;
    if (i < n) p[i] = 0;
}

// weight transpose + bf16 hi/lo split: W[K,N] fp32 -> hi/lo [N,K] bf16
__global__ void wsplit(const float* __restrict__ W, __nv_bfloat16* __restrict__ hi,
                       __nv_bfloat16* __restrict__ lo, int K, int N)
{
    int idx = blockIdx.x*blockDim.x + threadIdx.x;
    if (idx >= K*N) return;
    int k = idx / N, n = idx - k*N;
    float v = W[idx];
    __nv_bfloat16 h = __float2bfloat16(v);
    float r = v - __bfloat162float(h);
    hi[(long)n*K + k] = h;
    lo[(long)n*K + k] = __float2bfloat16(r);
}

// ---------------- WMMA bf16x3 GEMM ----------------
// C[M,N] = A1[M,K1]@W1^T + (A2[M,K2]@W2^T) (+bias) (+add)
// W pre-split bf16 hi/lo in [N,K]. Block tile 128x64, BK=32, 8 warps (4m x 2n),
// warp tile 32x32 of m16n16k16 fragments. fp32 accum, x3 products (hh, hl, lh).
#define WBM 128
#define WBN 64
#define WBK 32
#define SKA 40
#define SKB 40
#define SCC 72
#define MMA_SMEM 36864

typedef wmma::fragment<wmma::matrix_a, 16,16,16, __nv_bfloat16, wmma::row_major> FragA;
typedef wmma::fragment<wmma::matrix_b, 16,16,16, __nv_bfloat16, wmma::col_major> FragB;
typedef wmma::fragment<wmma::accumulator, 16,16,16, float> FragC;

__global__ void __launch_bounds__(256,2)
mma_gemm(const float* __restrict__ A1, const __nv_bfloat16* __restrict__ W1h,
         const __nv_bfloat16* __restrict__ W1l, int K1,
         const float* __restrict__ A2, const __nv_bfloat16* __restrict__ W2h,
         const __nv_bfloat16* __restrict__ W2l, int K2,
         const float* __restrict__ bias, const float* __restrict__ add,
         float* __restrict__ C, int M, int N)
{
    extern __shared__ char smc[];
    __nv_bfloat16* Ah = (__nv_bfloat16*)smc;          // 128*40
    __nv_bfloat16* Al = Ah + WBM*SKA;
    __nv_bfloat16* Bh = Al + WBM*SKA;                 // 64*40
    __nv_bfloat16* Bl = Bh + WBN*SKB;
    float* Cs = (float*)smc;                          // reuse: 128*72

    const int tid = threadIdx.x, wid = tid >> 5;
    const int warp_m = wid >> 1, warp_n = wid & 1;
    const int bm = blockIdx.y * WBM, bn = blockIdx.x * WBN;

    FragC acc[2][2];
    #pragma unroll
    for (int mm = 0; mm < 2; ++mm)
        #pragma unroll
        for (int nn = 0; nn < 2; ++nn)
            wmma::fill_fragment(acc[mm][nn], 0.f);

    #pragma unroll
    for (int pass = 0; pass < 2; ++pass) {
        const float* A = pass ? A2 : A1;
        if (A == nullptr) continue;
        const __nv_bfloat16* Wh = pass ? W2h : W1h;
        const __nv_bfloat16* Wl = pass ? W2l : W1l;
        const int K = pass ? K2 : K1;

        for (int k0 = 0; k0 < K; k0 += WBK) {
            // load A tile [128 x 32] fp32, split to bf16 hi/lo
            #pragma unroll
            for (int i = 0; i < 4; ++i) {
                int li = tid + (i << 8);
                int r = li >> 3, c = (li & 7) << 2;
                float4 v = make_float4(0.f,0.f,0.f,0.f);
                if (bm + r < M) v = *(const float4*)(A + (long)(bm+r)*K + k0 + c);
                __nv_bfloat16 hx = __float2bfloat16(v.x);
                __nv_bfloat16 hy = __float2bfloat16(v.y);
                __nv_bfloat16 hz = __float2bfloat16(v.z);
                __nv_bfloat16 hw = __float2bfloat16(v.w);
                int o = r*SKA + c;
                Ah[o]   = hx; Ah[o+1] = hy; Ah[o+2] = hz; Ah[o+3] = hw;
                Al[o]   = __float2bfloat16(v.x - __bfloat162float(hx));
                Al[o+1] = __float2bfloat16(v.y - __bfloat162float(hy));
                Al[o+2] = __float2bfloat16(v.z - __bfloat162float(hz));
                Al[o+3] = __float2bfloat16(v.w - __bfloat162float(hw));
            }
            // load B tile [64 n x 32 k] bf16 hi/lo (one uint4 = 8 bf16 each)
            {
                int r = tid >> 2, c = (tid & 3) << 3;
                long go = (long)(bn + r)*K + k0 + c;
                uint4 h = *(const uint4*)(Wh + go);
                uint4 l = *(const uint4*)(Wl + go);
                *(uint4*)&Bh[r*SKB + c] = h;
                *(uint4*)&Bl[r*SKB + c] = l;
            }
            __syncthreads();

            #pragma unroll
            for (int kk = 0; kk < WBK; kk += 16) {
                FragA ah[2], al[2];
                FragB bh[2], bl[2];
                #pragma unroll
                for (int mm = 0; mm < 2; ++mm) {
                    int ro = (warp_m*32 + mm*16)*SKA + kk;
                    wmma::load_matrix_sync(ah[mm], Ah + ro, SKA);
                    wmma::load_matrix_sync(al[mm], Al + ro, SKA);
                }
                #pragma unroll
                for (int nn = 0; nn < 2; ++nn) {
                    int no = (warp_n*32 + nn*16)*SKB + kk;
                    wmma::load_matrix_sync(bh[nn], Bh + no, SKB);
                    wmma::load_matrix_sync(bl[nn], Bl + no, SKB);
                }
                #pragma unroll
                for (int mm = 0; mm < 2; ++mm)
                    #pragma unroll
                    for (int nn = 0; nn < 2; ++nn) {
                        wmma::mma_sync(acc[mm][nn], ah[mm], bh[nn], acc[mm][nn]);
                        wmma::mma_sync(acc[mm][nn], ah[mm], bl[nn], acc[mm][nn]);
                        wmma::mma_sync(acc[mm][nn], al[mm], bh[nn], acc[mm][nn]);
                    }
            }
            __syncthreads();
        }
    }

    // epilogue: frags -> smem -> coalesced fp32 stores with bias/add
    #pragma unroll
    for (int mm = 0; mm < 2; ++mm)
        #pragma unroll
        for (int nn = 0; nn < 2; ++nn)
            wmma::store_matrix_sync(Cs + (warp_m*32 + mm*16)*SCC + warp_n*32 + nn*16,
                                    acc[mm][nn], SCC, wmma::mem_row_major);
    __syncthreads();

    #pragma unroll
    for (int i = 0; i < 8; ++i) {
        int li = tid + (i << 8);
        int r = li >> 4, c = (li & 15) << 2;
        long row = bm + r;
        if (row >= M) continue;
        float4 v = *(float4*)&Cs[r*SCC + c];
        int col = bn + c;
        if (bias) {
            float4 bb = *(const float4*)(bias + col);
            v.x += bb.x; v.y += bb.y; v.z += bb.z; v.w += bb.w;
        }
        if (add) {
            float4 aa = *(const float4*)(add + row*(long)N + col);
            v.x += aa.x; v.y += aa.y; v.z += aa.z; v.w += aa.w;
        }
        *(float4*)(C + row*(long)N + col) = v;
    }
}

// ---------------- SIMT GEMM (small shapes: dyn, fc) ----------------
#define BM 64
#define BN 64
#define BK 16
#define SPAD 4

template<int PRE, int ACT>
__global__ void gemm_k(const float* __restrict__ A,  const float* __restrict__ W1, int Ka,
                       const float* __restrict__ bias, const int* __restrict__ rowidx,
                       float* __restrict__ C, int M, int N)
{
    __shared__ float As[BK][BM+SPAD];
    __shared__ float Ws[BK][BN+SPAD];
    const int bm = blockIdx.y * BM, bn = blockIdx.x * BN;
    const int tid = threadIdx.x;
    const int tx = tid & 15, ty = tid >> 4;

    float acc[4][4] = {};

    const int ar = tid >> 2;
    const int ak = (tid & 3) << 2;
    const int wk = tid >> 4;
    const int wn = (tid & 15) << 2;

    const int arow_g = bm + ar;
    long arow = -1;
    if (arow_g < M) arow = rowidx ? (long)rowidx[arow_g] : (long)arow_g;

    for (int k0 = 0; k0 < Ka; k0 += BK) {
        float4 av = make_float4(0.f,0.f,0.f,0.f);
        if (arow >= 0) av = *(const float4*)(A + arow*(long)Ka + k0 + ak);
        if (PRE) { av.x=lk01(av.x); av.y=lk01(av.y); av.z=lk01(av.z); av.w=lk01(av.w); }
        As[ak  ][ar] = av.x;
        As[ak+1][ar] = av.y;
        As[ak+2][ar] = av.z;
        As[ak+3][ar] = av.w;
        float4 wv = *(const float4*)(W1 + (long)(k0+wk)*N + bn + wn);
        *(float4*)&Ws[wk][wn] = wv;
        __syncthreads();
        #pragma unroll
        for (int k = 0; k < BK; ++k) {
            float4 a4 = *(const float4*)&As[k][ty<<2];
            float4 b4 = *(const float4*)&Ws[k][tx<<2];
            acc[0][0]+=a4.x*b4.x; acc[0][1]+=a4.x*b4.y; acc[0][2]+=a4.x*b4.z; acc[0][3]+=a4.x*b4.w;
            acc[1][0]+=a4.y*b4.x; acc[1][1]+=a4.y*b4.y; acc[1][2]+=a4.y*b4.z; acc[1][3]+=a4.y*b4.w;
            acc[2][0]+=a4.z*b4.x; acc[2][1]+=a4.z*b4.y; acc[2][2]+=a4.z*b4.z; acc[2][3]+=a4.z*b4.w;
            acc[3][0]+=a4.w*b4.x; acc[3][1]+=a4.w*b4.y; acc[3][2]+=a4.w*b4.z; acc[3][3]+=a4.w*b4.w;
        }
        __syncthreads();
    }

    #pragma unroll
    for (int i = 0; i < 4; ++i) {
        int row = bm + (ty<<2) + i;
        if (row >= M) continue;
        #pragma unroll
        for (int j = 0; j < 4; ++j) {
            int col = bn + (tx<<2) + j;
            float v = acc[i][j];
            if (bias) v += bias[col];
            if (ACT == 1) v = lk01(v);
            C[(long)row*N + col] = v;
        }
    }
}

// ---------------- encoder ----------------
__global__ void emb_kernel(const float* __restrict__ x, const float* __restrict__ ipW,
                           const float* __restrict__ ipb)
{
    long i = (long)blockIdx.x*blockDim.x + threadIdx.x;
    if (i >= (long)NN*TT*DE) return;
    long row = i >> 5; int j = (int)(i & 31);
    float v = x[row*2]*ipW[j] + x[row*2+1]*ipW[DE+j] + ipb[j];
    g_EMB[i] = lk01(v);
}

__global__ void gru_gate(const float* __restrict__ Wx, const float* __restrict__ bx, int t)
{
    int i = blockIdx.x*blockDim.x + threadIdx.x;
    if (i >= NN*HE) return;
    int node = i >> 7, j = i & 127;
    const float* e = g_EMB + ((long)node*TT + t)*DE;
    float gr = bx[j], gz = bx[HE+j], gn = bx[2*HE+j];
    #pragma unroll
    for (int k = 0; k < DE; ++k) {
        float ev = e[k];
        const float* wr = Wx + k*F3;
        gr += ev*wr[j]; gz += ev*wr[HE+j]; gn += ev*wr[2*HE+j];
    }
    const float* gh = g_GH + (long)node*F3;
    float r = sigf(gr + gh[j]);
    float z = sigf(gz + gh[HE+j]);
    float n = tanhf(gn + r*gh[2*HE+j]);
    float h = g_H[i];
    g_H[i] = (1.f - z)*n + z*h;
}

// ---------------- CSR build ----------------
__global__ void edge_count(const int* __restrict__ ei){
    int e = blockIdx.x*blockDim.x + threadIdx.x;
    if (e >= NE) return;
    int d = (e < NE0) ? ei[NE0+e] : (e - NE0);
    atomicAdd(&g_cnt[d], 1);
}
__global__ void scan_kernel(){
    __shared__ int sh[1024];
    __shared__ int run;
    int tid = threadIdx.x;
    if (tid == 0) run = 0;
    __syncthreads();
    for (int base = 0; base < NN; base += 1024) {
        int v = (base + tid < NN) ? g_cnt[base + tid] : 0;
        sh[tid] = v; __syncthreads();
        for (int off = 1; off < 1024; off <<= 1) {
            int tv = (tid >= off) ? sh[tid-off] : 0;
            __syncthreads();
            sh[tid] += tv;
            __syncthreads();
        }
        if (base + tid < NN) g_offs[base + tid + 1] = run + sh[tid];
        __syncthreads();
        if (tid == 0) run += sh[1023];
        __syncthreads();
    }
    if (tid == 0) g_offs[0] = 0;
}
__global__ void copy_cur(){
    int i = blockIdx.x*blockDim.x + threadIdx.x;
    if (i < NN) g_cur[i] = g_offs[i];
}
__global__ void edge_scatter(const int* __restrict__ ei){
    int e = blockIdx.x*blockDim.x + threadIdx.x;
    if (e >= NE) return;
    int s, d;
    if (e < NE0) { s = ei[e]; d = ei[NE0+e]; } else { s = e - NE0; d = s; }
    int pos = atomicAdd(&g_cur[d], 1);
    g_ssrc[pos] = s;
}

// ---------------- GAT ----------------
__global__ void attn_coef(const float* __restrict__ F, const float* __restrict__ a_s,
                          const float* __restrict__ a_d)
{
    int w = (blockIdx.x*blockDim.x + threadIdx.x) >> 5;
    if (w >= NN*3) return;
    int lane = threadIdx.x & 31;
    int node = w / 3, h = w - node*3;
    const float* f = F + (long)node*F3 + h*HE;
    const float* As_ = a_s + h*HE;
    const float* Ad_ = a_d + h*HE;
    float s1 = 0.f, s2 = 0.f;
    #pragma unroll
    for (int c = lane; c < HE; c += 32) { float fv = f[c]; s1 += fv*As_[c]; s2 += fv*Ad_[c]; }
    #pragma unroll
    for (int o = 16; o; o >>= 1) {
        s1 += __shfl_down_sync(0xffffffffu, s1, o);
        s2 += __shfl_down_sync(0xffffffffu, s2, o);
    }
    if (lane == 0) { g_asv[w] = s1; g_adv[w] = s2; }
}

__global__ void gat_agg(const float* __restrict__ F, const float* __restrict__ bias,
                        float* __restrict__ O)
{
    int w = (blockIdx.x*blockDim.x + threadIdx.x) >> 5;
    if (w >= NN) return;
    int lane = threadIdx.x & 31;
    int beg = g_offs[w], end = g_offs[w+1];
    float ad0 = g_adv[w*3], ad1 = g_adv[w*3+1], ad2 = g_adv[w*3+2];
    float m0 = -1e30f, m1 = -1e30f, m2 = -1e30f;
    float d0 = 0.f, d1 = 0.f, d2 = 0.f;
    float acc[12];
    #pragma unroll
    for (int q = 0; q < 12; ++q) acc[q] = 0.f;

    for (int p = beg; p < end; ++p) {
        int s = g_ssrc[p];
        float e0 = g_asv[s*3]   + ad0; e0 = (e0 >= 0.f) ? e0 : 0.2f*e0;
        float e1 = g_asv[s*3+1] + ad1; e1 = (e1 >= 0.f) ? e1 : 0.2f*e1;
        float e2 = g_asv[s*3+2] + ad2; e2 = (e2 >= 0.f) ? e2 : 0.2f*e2;
        const float* f = F + (long)s*F3;
        {
            float nm = fmaxf(m0, e0); float sc = __expf(m0-nm); float wv = __expf(e0-nm);
            d0 = d0*sc + wv;
            #pragma unroll
            for (int q = 0; q < 4; ++q) acc[q] = acc[q]*sc + wv*f[q*32 + lane];
            m0 = nm;
        }
        {
            float nm = fmaxf(m1, e1); float sc = __expf(m1-nm); float wv = __expf(e1-nm);
            d1 = d1*sc + wv;
            #pragma unroll
            for (int q = 0; q < 4; ++q) acc[4+q] = acc[4+q]*sc + wv*f[HE + q*32 + lane];
            m1 = nm;
        }
        {
            float nm = fmaxf(m2, e2); float sc = __expf(m2-nm); float wv = __expf(e2-nm);
            d2 = d2*sc + wv;
            #pragma unroll
            for (int q = 0; q < 4; ++q) acc[8+q] = acc[8+q]*sc + wv*f[2*HE + q*32 + lane];
            m2 = nm;
        }
    }
    float* o = O + (long)w*F3;
    #pragma unroll
    for (int q = 0; q < 4; ++q) {
        int c0 = q*32 + lane;
        o[c0]        = acc[q]  /d0 + bias[c0];
        o[HE + c0]   = acc[4+q]/d1 + bias[HE + c0];
        o[2*HE + c0] = acc[8+q]/d2 + bias[2*HE + c0];
    }
}

// ---------------- decoder ----------------
__global__ void lstm_gate(const float* __restrict__ G, float* __restrict__ h, float* __restrict__ c)
{
    int i = blockIdx.x*blockDim.x + threadIdx.x;
    if (i >= NT*HD) return;
    int b = i >> 8, j = i & 255;
    const float* g = G + (long)b*(4*HD);
    float ig = sigf(g[j]);
    float fg = sigf(g[HD+j]);
    float gg = tanhf(g[2*HD+j]);
    float og = sigf(g[3*HD+j]);
    float cc = fg*c[i] + ig*gg;
    c[i] = cc;
    h[i] = og*tanhf(cc);
}

__global__ void out_head(const float* __restrict__ opW, const float* __restrict__ opb,
                         float* __restrict__ out, int t)
{
    int w = (blockIdx.x*blockDim.x + threadIdx.x) >> 5;
    if (w >= NT) return;
    int lane = threadIdx.x & 31;
    const float* h = g_h1 + (long)w*HD;
    float s0 = 0.f, s1 = 0.f;
    #pragma unroll
    for (int k = lane; k < HD; k += 32) {
        float hv = h[k];
        s0 += hv*opW[k*2];
        s1 += hv*opW[k*2+1];
    }
    #pragma unroll
    for (int o = 16; o; o >>= 1) {
        s0 += __shfl_down_sync(0xffffffffu, s0, o);
        s1 += __shfl_down_sync(0xffffffffu, s1, o);
    }
    if (lane == 0) {
        long base = ((long)w*OUTL + t)*2;
        out[base]   = s0 + opb[0];
        out[base+1] = s1 + opb[1];
    }
}

// ---------------- host orchestration ----------------
static inline void mmagemm(const float* A1, const __nv_bfloat16* W1h, const __nv_bfloat16* W1l, int K1,
                           const float* A2, const __nv_bfloat16* W2h, const __nv_bfloat16* W2l, int K2,
                           const float* bias, const float* add, float* C, int M, int N)
{
    dim3 g(N/WBN, (M + WBM - 1)/WBM);
    mma_gemm<<<g, 256, MMA_SMEM>>>(A1, W1h, W1l, K1, A2, W2h, W2l, K2, bias, add, C, M, N);
}

extern "C" void kernel_launch(void* const* d_in, const int* in_sizes, int n_in,
                              void* d_out, int out_size)
{
    const float* x    = (const float*)d_in[0];
    const int*   ei   = (const int*)  d_in[1];
    const int*   tgt  = (const int*)  d_in[2];
    const float* ipW  = (const float*)d_in[3];
    const float* ipb  = (const float*)d_in[4];
    const float* gWx  = (const float*)d_in[5];
    const float* gWh  = (const float*)d_in[6];
    const float* gbx  = (const float*)d_in[7];
    const float* gbh  = (const float*)d_in[8];
    const float* dynW = (const float*)d_in[9];
    const float* dynb = (const float*)d_in[10];
    const float* g1W  = (const float*)d_in[11];
    const float* g1as = (const float*)d_in[12];
    const float* g1ad = (const float*)d_in[13];
    const float* g1b  = (const float*)d_in[14];
    const float* g2W  = (const float*)d_in[15];
    const float* g2as = (const float*)d_in[16];
    const float* g2ad = (const float*)d_in[17];
    const float* g2b  = (const float*)d_in[18];
    const float* fcW  = (const float*)d_in[19];
    const float* fcb  = (const float*)d_in[20];
    const float* l0Wx = (const float*)d_in[21];
    const float* l0Wh = (const float*)d_in[22];
    const float* l0b  = (const float*)d_in[23];
    const float* l1Wx = (const float*)d_in[24];
    const float* l1Wh = (const float*)d_in[25];
    const float* l1b  = (const float*)d_in[26];
    const float* opW  = (const float*)d_in[27];
    const float* opb  = (const float*)d_in[28];
    float* out = (float*)d_out;
    (void)in_sizes; (void)n_in; (void)out_size;

    float *EMB,*H,*GH,*HENC,*F1,*O1,*F2,*O2,*ENC,*X0,*G,*h0,*c0,*h1,*c1;
    __nv_bfloat16 *WTh,*WTl;
    cudaGetSymbolAddress((void**)&EMB,  g_EMB);
    cudaGetSymbolAddress((void**)&H,    g_H);
    cudaGetSymbolAddress((void**)&GH,   g_GH);
    cudaGetSymbolAddress((void**)&HENC, g_HENC);
    cudaGetSymbolAddress((void**)&F1,   g_F1);
    cudaGetSymbolAddress((void**)&O1,   g_O1);
    cudaGetSymbolAddress((void**)&F2,   g_F2);
    cudaGetSymbolAddress((void**)&O2,   g_O2);
    cudaGetSymbolAddress((void**)&ENC,  g_ENC);
    cudaGetSymbolAddress((void**)&X0,   g_X0);
    cudaGetSymbolAddress((void**)&G,    g_G);
    cudaGetSymbolAddress((void**)&h0,   g_h0);
    cudaGetSymbolAddress((void**)&c0,   g_c0);
    cudaGetSymbolAddress((void**)&h1,   g_h1);
    cudaGetSymbolAddress((void**)&c1,   g_c1);
    cudaGetSymbolAddress((void**)&WTh,  g_WThi);
    cudaGetSymbolAddress((void**)&WTl,  g_WTlo);
    int *cntp;
    cudaGetSymbolAddress((void**)&cntp, g_cnt);

    // transposed bf16 hi/lo weight offsets (elements)
    const int o_gWh  = 0;
    const int o_g1W  = 49152;
    const int o_g2W  = 98304;
    const int o_l0Wx = 245760;
    const int o_l0Wh = 376832;
    const int o_l1Wx = 638976;
    const int o_l1Wh = 901120;

    // ---- weight prep ----
    wsplit<<<(128*384+255)/256,256>>>(gWh,  WTh+o_gWh,  WTl+o_gWh,  128, 384);
    wsplit<<<(128*384+255)/256,256>>>(g1W,  WTh+o_g1W,  WTl+o_g1W,  128, 384);
    wsplit<<<(384*384+255)/256,256>>>(g2W,  WTh+o_g2W,  WTl+o_g2W,  384, 384);
    wsplit<<<(128*1024+255)/256,256>>>(l0Wx, WTh+o_l0Wx, WTl+o_l0Wx, 128, 1024);
    wsplit<<<(256*1024+255)/256,256>>>(l0Wh, WTh+o_l0Wh, WTl+o_l0Wh, 256, 1024);
    wsplit<<<(256*1024+255)/256,256>>>(l1Wx, WTh+o_l1Wx, WTl+o_l1Wx, 256, 1024);
    wsplit<<<(256*1024+255)/256,256>>>(l1Wh, WTh+o_l1Wh, WTl+o_l1Wh, 256, 1024);

    // ---- CSR build ----
    zero_i<<<(NN+255)/256,256>>>(cntp, NN);
    edge_count<<<(NE+255)/256,256>>>(ei);
    scan_kernel<<<1,1024>>>();
    copy_cur<<<(NN+255)/256,256>>>();
    edge_scatter<<<(NE+255)/256,256>>>(ei);

    // ---- encoder: emb + GRU ----
    emb_kernel<<<(int)(((long)NN*TT*DE + 255)/256),256>>>(x, ipW, ipb);
    zero_f<<<(int)(((long)NN*HE + 255)/256),256>>>(H, (long)NN*HE);
    for (int t = 0; t < TT; ++t) {
        mmagemm(H, WTh+o_gWh, WTl+o_gWh, HE, nullptr,nullptr,nullptr,0, gbh, nullptr, GH, NN, F3);
        gru_gate<<<(NN*HE+255)/256,256>>>(gWx, gbx, t);
    }
    // hist_enc = leaky( leaky(H) @ dynW + dynb )   (SIMT: PRE+ACT)
    {
        dim3 g(HE/BN, (NN+BM-1)/BM);
        gemm_k<1,1><<<g,256>>>(H, dynW, HE, dynb, nullptr, HENC, NN, HE);
    }

    // ---- GAT layer 1 ----
    mmagemm(HENC, WTh+o_g1W, WTl+o_g1W, HE, nullptr,nullptr,nullptr,0, nullptr, nullptr, F1, NN, F3);
    attn_coef<<<(NN*3*32+255)/256,256>>>(F1, g1as, g1ad);
    gat_agg<<<(NN*32+255)/256,256>>>(F1, g1b, O1);

    // ---- GAT layer 2 ----
    mmagemm(O1, WTh+o_g2W, WTl+o_g2W, F3, nullptr,nullptr,nullptr,0, nullptr, nullptr, F2, NN, F3);
    attn_coef<<<(NN*3*32+255)/256,256>>>(F2, g2as, g2ad);
    gat_agg<<<(NN*32+255)/256,256>>>(F2, g2b, O2);

    // ---- target gather + fc (SIMT: gather + act) ----
    {
        dim3 g(HE/BN, (NT+BM-1)/BM);
        gemm_k<0,1><<<g,256>>>(O2, fcW, F3, fcb, tgt, ENC, NT, HE);
    }

    // ---- decoder ----
    mmagemm(ENC, WTh+o_l0Wx, WTl+o_l0Wx, HE, nullptr,nullptr,nullptr,0, l0b, nullptr, X0, NT, 4*HD);
    zero_f<<<((NT*HD)+255)/256,256>>>(h0, (long)NT*HD);
    zero_f<<<((NT*HD)+255)/256,256>>>(c0, (long)NT*HD);
    zero_f<<<((NT*HD)+255)/256,256>>>(h1, (long)NT*HD);
    zero_f<<<((NT*HD)+255)/256,256>>>(c1, (long)NT*HD);

    for (int t = 0; t < OUTL; ++t) {
        mmagemm(h0, WTh+o_l0Wh, WTl+o_l0Wh, HD, nullptr,nullptr,nullptr,0, nullptr, X0, G, NT, 4*HD);
        lstm_gate<<<(NT*HD+255)/256,256>>>(G, h0, c0);
        mmagemm(h0, WTh+o_l1Wx, WTl+o_l1Wx, HD, h1, WTh+o_l1Wh, WTl+o_l1Wh, HD, l1b, nullptr, G, NT, 4*HD);
        lstm_gate<<<(NT*HD+255)/256,256>>>(G, h1, c1);
        out_head<<<(NT*32+255)/256,256>>>(opW, opb, out, t);
    }
}